// round 2
// baseline (speedup 1.0000x reference)
#include <cuda_runtime.h>
#include <math.h>

// ---------------- static scratch (no runtime allocation allowed) ----------------
#define TBL_N    32768
#define TBL_MAX  8.0f
#define NMAX     65536
#define EMAX     1700000

__device__ float4 g_table[TBL_N];          // (alpha,gamma,delta,beta') gate coeffs
__device__ float  g_Ai[NMAX * 8];          // per-node scalar features
__device__ int    g_cnt[NMAX];             // edge counts per dst
__device__ int    g_off[NMAX + 1];         // CSR offsets
__device__ int    g_cur[NMAX];             // scatter cursors
__device__ float4 g_pay[(size_t)EMAX * 4]; // per-edge payload: s[8], Ai[8] (64B)

__device__ __forceinline__ float siluf(float x) { return x / (1.0f + expf(-x)); }

// ---------------- K1: fused prep (gate table | node MLP | zero counts) ----------------
__global__ void prep_kernel(const float* __restrict__ f1, const float* __restrict__ fb1,
                            const float* __restrict__ f2, const float* __restrict__ fb2,
                            const float* __restrict__ f3, const float* __restrict__ fb3,
                            const float* __restrict__ emb_table, const int* __restrict__ A,
                            const float* __restrict__ w1, const float* __restrict__ b1,
                            const float* __restrict__ w2, const float* __restrict__ b2,
                            int N)
{
    int tid = threadIdx.x;
    int bx = blockIdx.x;
    int nbNode = (N + 255) / 256;

    if (bx < 128) {
        // ---- gate table role ----
        __shared__ float sf1[16 * 64];
        __shared__ float sf2[64 * 64];
        __shared__ float sf3[64 * 5];
        __shared__ float sb1[64], sb2[64], sb3[5];
        for (int i = tid; i < 16 * 64; i += 256) sf1[i] = f1[i];
        for (int i = tid; i < 64 * 64; i += 256) sf2[i] = f2[i];
        for (int i = tid; i < 64 * 5;  i += 256) sf3[i] = f3[i];
        if (tid < 64) { sb1[tid] = fb1[tid]; sb2[tid] = fb2[tid]; }
        if (tid < 5)  sb3[tid] = fb3[tid];
        __syncthreads();

        int idx = bx * 256 + tid;
        float x = (float)idx * (TBL_MAX / (float)TBL_N);
        float emb[16];
#pragma unroll
        for (int k = 0; k < 16; k++) {
            float c = (5.0f / 17.0f) * (float)(k + 1);
            float z = (x - c) * (17.0f / 5.0f);
            emb[k] = 3.57142857142857f * expf(-z * z);
        }
        float h1[64];
        for (int j = 0; j < 64; j++) {
            float a = sb1[j];
#pragma unroll
            for (int k = 0; k < 16; k++) a = fmaf(emb[k], sf1[k * 64 + j], a);
            h1[j] = siluf(a);
        }
        float g0 = sb3[0], g1 = sb3[1], g2 = sb3[2], g3 = sb3[3];
        for (int j = 0; j < 64; j++) {
            float a = sb2[j];
#pragma unroll 8
            for (int k = 0; k < 64; k++) a = fmaf(h1[k], sf2[k * 64 + j], a);
            float h = siluf(a);
            g0 = fmaf(h, sf3[j * 5 + 0], g0);
            g1 = fmaf(h, sf3[j * 5 + 1], g1);
            g2 = fmaf(h, sf3[j * 5 + 2], g2);
            g3 = fmaf(h, sf3[j * 5 + 3], g3);
            // path (1,1,1): eps_mno n_m n_n == 0 -> dead, g4 never needed
        }
        const float IS8 = 0.3535533905932738f;
        const float IS3 = 0.5773502691896258f;
        float4 T;
        T.x = g0 * IS8;          // alpha
        T.y = g1 * IS8;          // gamma
        T.z = g2 * IS8;          // delta
        T.w = g3 * IS8 * IS3;    // beta (pre s2)
        g_table[idx] = T;
    } else if (bx < 128 + nbNode) {
        // ---- node MLP role ----
        __shared__ float sw1[16 * 64];
        __shared__ float sw2[64 * 8];
        __shared__ float nb1[64], nb2[8];
        for (int i = tid; i < 16 * 64; i += 256) sw1[i] = w1[i];
        for (int i = tid; i < 64 * 8;  i += 256) sw2[i] = w2[i];
        if (tid < 64) nb1[tid] = b1[tid];
        if (tid < 8)  nb2[tid] = b2[tid];
        __syncthreads();

        int n = (bx - 128) * 256 + tid;
        if (n >= N) return;
        int a = A[n];
        const float4* ep = (const float4*)(emb_table + (size_t)a * 16);
        float4 e0 = __ldg(ep + 0), e1 = __ldg(ep + 1), e2 = __ldg(ep + 2), e3 = __ldg(ep + 3);
        float e[16] = { e0.x, e0.y, e0.z, e0.w, e1.x, e1.y, e1.z, e1.w,
                        e2.x, e2.y, e2.z, e2.w, e3.x, e3.y, e3.z, e3.w };
        float acc[8];
#pragma unroll
        for (int u = 0; u < 8; u++) acc[u] = nb2[u];
        for (int j = 0; j < 64; j++) {
            float h = nb1[j];
#pragma unroll
            for (int k = 0; k < 16; k++) h = fmaf(e[k], sw1[k * 64 + j], h);
            h = siluf(h);
#pragma unroll
            for (int u = 0; u < 8; u++) acc[u] = fmaf(h, sw2[j * 8 + u], acc[u]);
        }
        float4* op = (float4*)(g_Ai + (size_t)n * 8);
        op[0] = make_float4(acc[0], acc[1], acc[2], acc[3]);
        op[1] = make_float4(acc[4], acc[5], acc[6], acc[7]);
    } else {
        // ---- zero counters role ----
        int zb = bx - 128 - nbNode;
        int i0 = zb * 2048 + tid * 8;
        if (i0 + 7 < N) {
            *(int4*)(g_cnt + i0)     = make_int4(0, 0, 0, 0);
            *(int4*)(g_cnt + i0 + 4) = make_int4(0, 0, 0, 0);
        } else {
            for (int i = i0; i < N; i++) g_cnt[i] = 0;
        }
    }
}

// ---------------- K2: count edges per dst ----------------
__global__ void count_kernel(const int* __restrict__ edst, int E)
{
    int i = (blockIdx.x * blockDim.x + threadIdx.x) * 4;
    if (i + 3 < E) {
        int4 d = *(const int4*)(edst + i);
        atomicAdd(&g_cnt[d.x], 1);
        atomicAdd(&g_cnt[d.y], 1);
        atomicAdd(&g_cnt[d.z], 1);
        atomicAdd(&g_cnt[d.w], 1);
    } else {
        for (int k = i; k < E; k++) atomicAdd(&g_cnt[edst[k]], 1);
    }
}

// ---------------- K3: exclusive scan of counts -> offsets + cursors ----------------
__global__ void scan_kernel(int N)
{
    __shared__ int sm[1024];
    int tid = threadIdx.x;
    int chunk = (N + 1023) >> 10;
    int s = tid * chunk;
    int e = min(s + chunk, N);
    int sum = 0;
    for (int i = s; i < e; i++) sum += g_cnt[i];
    sm[tid] = sum;
    __syncthreads();
    // Hillis-Steele inclusive scan
    for (int d = 1; d < 1024; d <<= 1) {
        int t = (tid >= d) ? sm[tid - d] : 0;
        __syncthreads();
        sm[tid] += t;
        __syncthreads();
    }
    int p = sm[tid] - sum;   // exclusive prefix
    for (int i = s; i < e; i++) {
        g_off[i] = p;
        g_cur[i] = p;
        p += g_cnt[i];
    }
    if (tid == 1023) g_off[N] = sm[1023];
}

// ---------------- K4: edge geometry + gate lookup + payload scatter ----------------
__global__ void __launch_bounds__(256) scatter_kernel(
    const float* __restrict__ pos, const int* __restrict__ esrc, const int* __restrict__ edst,
    const float* __restrict__ shifts, const float* __restrict__ cell, int E)
{
    int e = blockIdx.x * blockDim.x + threadIdx.x;
    if (e >= E) return;
    int s = esrc[e];
    int d = edst[e];

    float shx = shifts[3 * e + 0], shy = shifts[3 * e + 1], shz = shifts[3 * e + 2];
    float vx = __ldg(pos + 3 * d + 0) - __ldg(pos + 3 * s + 0)
             + shx * __ldg(cell + 0) + shy * __ldg(cell + 3) + shz * __ldg(cell + 6);
    float vy = __ldg(pos + 3 * d + 1) - __ldg(pos + 3 * s + 1)
             + shx * __ldg(cell + 1) + shy * __ldg(cell + 4) + shz * __ldg(cell + 7);
    float vz = __ldg(pos + 3 * d + 2) - __ldg(pos + 3 * s + 2)
             + shx * __ldg(cell + 2) + shy * __ldg(cell + 5) + shz * __ldg(cell + 8);

    float len = sqrtf(vx * vx + vy * vy + vz * vz);
    float inv = 1.0f / fmaxf(len, 1e-8f);
    float nx = vx * inv, ny = vy * inv, nz = vz * inv;
    float s2 = nx * nx + ny * ny + nz * nz;   // 1 except degenerate edges

    float t = fminf(len * ((float)TBL_N / TBL_MAX), (float)TBL_N - 1.001f);
    int   i0 = (int)t;
    float fr = t - (float)i0;
    float4 Ta = __ldg(&g_table[i0]);
    float4 Tb = __ldg(&g_table[i0 + 1]);
    float alpha = fmaf(fr, Tb.x - Ta.x, Ta.x);
    float gamma = fmaf(fr, Tb.y - Ta.y, Ta.y);
    float delta = fmaf(fr, Tb.z - Ta.z, Ta.z);
    float beta  = fmaf(fr, Tb.w - Ta.w, Ta.w) * s2;

    const float4* aip = (const float4*)(g_Ai + (size_t)s * 8);
    float4 A0 = __ldg(aip + 0);
    float4 A1 = __ldg(aip + 1);

    int slot = atomicAdd(&g_cur[d], 1);
    float4* P = g_pay + (size_t)slot * 4;
    P[0] = make_float4(alpha, beta, gamma * nx, gamma * ny);
    P[1] = make_float4(gamma * nz, delta * nx, delta * ny, delta * nz);
    P[2] = A0;
    P[3] = A1;
}

// ---------------- K5: CSR gather + apply path weights, write [N,128] ----------------
__global__ void __launch_bounds__(256) gather_kernel(
    const float* __restrict__ tpw, float* __restrict__ out, int N, float scale)
{
    __shared__ float sW[1024];         // tpw[4 paths][8][32] (path 4 unused but loaded)
    __shared__ float sS[4][32][8];
    __shared__ float sA[4][32][8];
    __shared__ float accS[4][64];
    __shared__ int   sDeg[4];

    int tid = threadIdx.x;
    for (int i = tid; i < 1024; i += 256) sW[i] = __ldg(tpw + i);

    int slot = tid >> 6;
    int t = tid & 63;
    int node = blockIdx.x * 4 + slot;

    int base = 0, deg = 0;
    if (node < N) {
        base = g_off[node];
        deg = g_off[node + 1] - base;
    }
    if (t == 0) sDeg[slot] = deg;
    __syncthreads();
    int maxdeg = max(max(sDeg[0], sDeg[1]), max(sDeg[2], sDeg[3]));
    int nch = (maxdeg + 31) >> 5;

    int j = t >> 3, u = t & 7;
    float acc = 0.0f;

    for (int ch = 0; ch < nch; ch++) {
        int c0 = ch * 32;
        int m = deg - c0;
        if (m > 32) m = 32;
        if (t < m) {
            const float4* P = g_pay + (size_t)(base + c0 + t) * 4;
            float4 p0 = P[0], p1 = P[1], p2 = P[2], p3 = P[3];
            *(float4*)&sS[slot][t][0] = p0;
            *(float4*)&sS[slot][t][4] = p1;
            *(float4*)&sA[slot][t][0] = p2;
            *(float4*)&sA[slot][t][4] = p3;
        }
        __syncthreads();
        int mm = m > 0 ? m : 0;
        for (int c = 0; c < mm; c++)
            acc = fmaf(sS[slot][c][j], sA[slot][c][u], acc);
        __syncthreads();
    }

    accS[slot][t] = acc;   // t = j*8 + u
    __syncthreads();

    if (node >= N) return;

    // each thread computes output columns t and t+64
#pragma unroll
    for (int half = 0; half < 2; half++) {
        int col = t + half * 64;
        float sum = 0.0f;
        if (col < 32) {
            int v = col;
#pragma unroll
            for (int uu = 0; uu < 8; uu++) {
                sum = fmaf(sW[0 * 256 + uu * 32 + v], accS[slot][0 * 8 + uu], sum);   // W0 * alpha row
                sum = fmaf(sW[3 * 256 + uu * 32 + v], accS[slot][1 * 8 + uu], sum);   // W3 * beta row
            }
        } else {
            int q = col - 32;
            int v = q / 3;
            int o = q - 3 * v;
#pragma unroll
            for (int uu = 0; uu < 8; uu++) {
                sum = fmaf(sW[1 * 256 + uu * 32 + v], accS[slot][(2 + o) * 8 + uu], sum);  // W1 * gamma*n_o
                sum = fmaf(sW[2 * 256 + uu * 32 + v], accS[slot][(5 + o) * 8 + uu], sum);  // W2 * delta*n_o
            }
        }
        out[(size_t)node * 128 + col] = sum * scale;
    }
}

// ---------------- launch ----------------
extern "C" void kernel_launch(void* const* d_in, const int* in_sizes, int n_in,
                              void* d_out, int out_size)
{
    const float* pos       = (const float*)d_in[0];
    const int*   A         = (const int*)  d_in[1];
    const int*   esrc      = (const int*)  d_in[3];
    const int*   edst      = (const int*)  d_in[4];
    const float* shifts    = (const float*)d_in[5];
    const float* cell      = (const float*)d_in[6];
    const float* emb_table = (const float*)d_in[7];
    const float* w1  = (const float*)d_in[8];
    const float* b1  = (const float*)d_in[9];
    const float* w2  = (const float*)d_in[10];
    const float* b2  = (const float*)d_in[11];
    const float* f1  = (const float*)d_in[12];
    const float* fb1 = (const float*)d_in[13];
    const float* f2  = (const float*)d_in[14];
    const float* fb2 = (const float*)d_in[15];
    const float* f3  = (const float*)d_in[16];
    const float* fb3 = (const float*)d_in[17];
    const float* tpw = (const float*)d_in[18];

    int N = in_sizes[1];
    int E = in_sizes[3];

    int nbNode = (N + 255) / 256;
    int nbZero = (N + 2047) / 2048;
    prep_kernel<<<128 + nbNode + nbZero, 256>>>(f1, fb1, f2, fb2, f3, fb3,
                                                emb_table, A, w1, b1, w2, b2, N);
    count_kernel<<<(E / 4 + 255) / 256 + 1, 256>>>(edst, E);
    scan_kernel<<<1, 1024>>>(N);
    scatter_kernel<<<(E + 255) / 256, 256>>>(pos, esrc, edst, shifts, cell, E);
    gather_kernel<<<(N + 3) / 4, 256>>>(tpw, (float*)d_out, N, (float)N / (float)E);
}

// round 3
// speedup vs baseline: 1.1129x; 1.1129x over previous
#include <cuda_runtime.h>
#include <math.h>

// ---------------- static scratch (no runtime allocation allowed) ----------------
#define TBL_N    32768
#define TBL_MAX  8.0f
#define NMAX     65536
#define EMAX     1700000

__device__ float4 g_table[TBL_N];            // (alpha,gamma,delta,beta') gate coeffs
__device__ float4 g_node[NMAX * 3];          // per node: {pos,_}, {Ai0-3}, {Ai4-7}
__device__ int    g_cnt[NMAX];               // edge counts per dst
__device__ int    g_off[NMAX + 1];           // CSR offsets
__device__ int    g_cur[NMAX];               // scatter cursors
__device__ int    g_cellflag;                // 1 if cell has any nonzero entry
__device__ float4 g_pay[(size_t)EMAX * 4];   // per-edge payload: s[8], Ai[8] (64B)

__device__ __forceinline__ float siluf(float x) { return x / (1.0f + expf(-x)); }

// ---------------- K1: fused prep (gate table | node pack+MLP | zero counts) ----------------
__global__ void prep_kernel(const float* __restrict__ f1, const float* __restrict__ fb1,
                            const float* __restrict__ f2, const float* __restrict__ fb2,
                            const float* __restrict__ f3, const float* __restrict__ fb3,
                            const float* __restrict__ emb_table, const int* __restrict__ A,
                            const float* __restrict__ w1, const float* __restrict__ b1,
                            const float* __restrict__ w2, const float* __restrict__ b2,
                            const float* __restrict__ pos, const float* __restrict__ cell,
                            int N)
{
    int tid = threadIdx.x;
    int bx = blockIdx.x;
    int nbNode = (N + 255) / 256;

    if (bx < 128) {
        // ---- gate table role ----
        if (bx == 0 && tid == 0) {
            int fl = 0;
            for (int i = 0; i < 9; i++) fl |= (cell[i] != 0.0f);
            g_cellflag = fl;
        }
        __shared__ float sf1[16 * 64];
        __shared__ float sf2[64 * 64];
        __shared__ float sf3[64 * 5];
        __shared__ float sb1[64], sb2[64], sb3[5];
        for (int i = tid; i < 16 * 64; i += 256) sf1[i] = f1[i];
        for (int i = tid; i < 64 * 64; i += 256) sf2[i] = f2[i];
        for (int i = tid; i < 64 * 5;  i += 256) sf3[i] = f3[i];
        if (tid < 64) { sb1[tid] = fb1[tid]; sb2[tid] = fb2[tid]; }
        if (tid < 5)  sb3[tid] = fb3[tid];
        __syncthreads();

        int idx = bx * 256 + tid;
        float x = (float)idx * (TBL_MAX / (float)TBL_N);
        float emb[16];
#pragma unroll
        for (int k = 0; k < 16; k++) {
            float c = (5.0f / 17.0f) * (float)(k + 1);
            float z = (x - c) * (17.0f / 5.0f);
            emb[k] = 3.57142857142857f * expf(-z * z);
        }
        float h1[64];
        for (int j = 0; j < 64; j++) {
            float a = sb1[j];
#pragma unroll
            for (int k = 0; k < 16; k++) a = fmaf(emb[k], sf1[k * 64 + j], a);
            h1[j] = siluf(a);
        }
        float g0 = sb3[0], g1 = sb3[1], g2 = sb3[2], g3 = sb3[3];
        for (int j = 0; j < 64; j++) {
            float a = sb2[j];
#pragma unroll 8
            for (int k = 0; k < 64; k++) a = fmaf(h1[k], sf2[k * 64 + j], a);
            float h = siluf(a);
            g0 = fmaf(h, sf3[j * 5 + 0], g0);
            g1 = fmaf(h, sf3[j * 5 + 1], g1);
            g2 = fmaf(h, sf3[j * 5 + 2], g2);
            g3 = fmaf(h, sf3[j * 5 + 3], g3);
            // path (1,1,1): eps_mno n_m n_n == 0 -> dead, g4 never needed
        }
        const float IS8 = 0.3535533905932738f;
        const float IS3 = 0.5773502691896258f;
        float4 T;
        T.x = g0 * IS8;          // alpha
        T.y = g1 * IS8;          // gamma
        T.z = g2 * IS8;          // delta
        T.w = g3 * IS8 * IS3;    // beta (pre s2)
        g_table[idx] = T;
    } else if (bx < 128 + nbNode) {
        // ---- node MLP + pack role ----
        __shared__ float sw1[16 * 64];
        __shared__ float sw2[64 * 8];
        __shared__ float nb1[64], nb2[8];
        for (int i = tid; i < 16 * 64; i += 256) sw1[i] = w1[i];
        for (int i = tid; i < 64 * 8;  i += 256) sw2[i] = w2[i];
        if (tid < 64) nb1[tid] = b1[tid];
        if (tid < 8)  nb2[tid] = b2[tid];
        __syncthreads();

        int n = (bx - 128) * 256 + tid;
        if (n >= N) return;
        int a = A[n];
        const float4* ep = (const float4*)(emb_table + (size_t)a * 16);
        float4 e0 = __ldg(ep + 0), e1 = __ldg(ep + 1), e2 = __ldg(ep + 2), e3 = __ldg(ep + 3);
        float e[16] = { e0.x, e0.y, e0.z, e0.w, e1.x, e1.y, e1.z, e1.w,
                        e2.x, e2.y, e2.z, e2.w, e3.x, e3.y, e3.z, e3.w };
        float acc[8];
#pragma unroll
        for (int u = 0; u < 8; u++) acc[u] = nb2[u];
        for (int j = 0; j < 64; j++) {
            float h = nb1[j];
#pragma unroll
            for (int k = 0; k < 16; k++) h = fmaf(e[k], sw1[k * 64 + j], h);
            h = siluf(h);
#pragma unroll
            for (int u = 0; u < 8; u++) acc[u] = fmaf(h, sw2[j * 8 + u], acc[u]);
        }
        g_node[3 * n + 0] = make_float4(pos[3 * n], pos[3 * n + 1], pos[3 * n + 2], 0.f);
        g_node[3 * n + 1] = make_float4(acc[0], acc[1], acc[2], acc[3]);
        g_node[3 * n + 2] = make_float4(acc[4], acc[5], acc[6], acc[7]);
    } else {
        // ---- zero counters role ----
        int zb = bx - 128 - nbNode;
        int i0 = zb * 2048 + tid * 8;
        if (i0 + 7 < N) {
            *(int4*)(g_cnt + i0)     = make_int4(0, 0, 0, 0);
            *(int4*)(g_cnt + i0 + 4) = make_int4(0, 0, 0, 0);
        } else {
            for (int i = i0; i < N; i++) g_cnt[i] = 0;
        }
    }
}

// ---------------- K2: count edges per dst ----------------
__global__ void count_kernel(const int* __restrict__ edst, int E)
{
    int i = (blockIdx.x * blockDim.x + threadIdx.x) * 4;
    if (i + 3 < E) {
        int4 d = *(const int4*)(edst + i);
        atomicAdd(&g_cnt[d.x], 1);
        atomicAdd(&g_cnt[d.y], 1);
        atomicAdd(&g_cnt[d.z], 1);
        atomicAdd(&g_cnt[d.w], 1);
    } else {
        for (int k = i; k < E; k++) atomicAdd(&g_cnt[edst[k]], 1);
    }
}

// ---------------- K3: exclusive scan of counts -> offsets + cursors ----------------
__global__ void scan_kernel(int N)
{
    __shared__ int sm[1024];
    int tid = threadIdx.x;
    int chunk = (N + 1023) >> 10;
    int s = tid * chunk;
    int e = min(s + chunk, N);
    int sum = 0;
    for (int i = s; i < e; i++) sum += g_cnt[i];
    sm[tid] = sum;
    __syncthreads();
    for (int d = 1; d < 1024; d <<= 1) {
        int t = (tid >= d) ? sm[tid - d] : 0;
        __syncthreads();
        sm[tid] += t;
        __syncthreads();
    }
    int p = sm[tid] - sum;   // exclusive prefix
    for (int i = s; i < e; i++) {
        g_off[i] = p;
        g_cur[i] = p;
        p += g_cnt[i];
    }
    if (tid == 1023) g_off[N] = sm[1023];
}

// ---------------- K4: edge geometry + gate lookup + payload scatter ----------------
__global__ void __launch_bounds__(256) scatter_kernel(
    const int* __restrict__ esrc, const int* __restrict__ edst,
    const float* __restrict__ shifts, const float* __restrict__ cell, int E)
{
    int e = blockIdx.x * blockDim.x + threadIdx.x;
    if (e >= E) return;
    int s = esrc[e];
    int d = edst[e];

    float4 ps = __ldg(&g_node[3 * s]);
    float4 pd = __ldg(&g_node[3 * d]);
    float vx = pd.x - ps.x;
    float vy = pd.y - ps.y;
    float vz = pd.z - ps.z;

    if (g_cellflag) {   // exact: when cell==0, shift contribution is identically 0
        float shx = shifts[3 * e + 0], shy = shifts[3 * e + 1], shz = shifts[3 * e + 2];
        vx += shx * __ldg(cell + 0) + shy * __ldg(cell + 3) + shz * __ldg(cell + 6);
        vy += shx * __ldg(cell + 1) + shy * __ldg(cell + 4) + shz * __ldg(cell + 7);
        vz += shx * __ldg(cell + 2) + shy * __ldg(cell + 5) + shz * __ldg(cell + 8);
    }

    float len = sqrtf(vx * vx + vy * vy + vz * vz);
    float inv = 1.0f / fmaxf(len, 1e-8f);
    float nx = vx * inv, ny = vy * inv, nz = vz * inv;
    float s2 = nx * nx + ny * ny + nz * nz;   // 1 except degenerate edges

    float t = fminf(len * ((float)TBL_N / TBL_MAX), (float)TBL_N - 1.001f);
    int   i0 = (int)t;
    float fr = t - (float)i0;
    float4 Ta = __ldg(&g_table[i0]);
    float4 Tb = __ldg(&g_table[i0 + 1]);
    float alpha = fmaf(fr, Tb.x - Ta.x, Ta.x);
    float gamma = fmaf(fr, Tb.y - Ta.y, Ta.y);
    float delta = fmaf(fr, Tb.z - Ta.z, Ta.z);
    float beta  = fmaf(fr, Tb.w - Ta.w, Ta.w) * s2;

    float4 A0 = __ldg(&g_node[3 * s + 1]);
    float4 A1 = __ldg(&g_node[3 * s + 2]);

    int slot = atomicAdd(&g_cur[d], 1);
    float4* P = g_pay + (size_t)slot * 4;
    P[0] = make_float4(alpha, beta, gamma * nx, gamma * ny);
    P[1] = make_float4(gamma * nz, delta * nx, delta * ny, delta * nz);
    P[2] = A0;
    P[3] = A1;
}

// ---------------- K5: CSR gather (1 thread/node, reg acc) + fused finalize ----------------
__global__ void __launch_bounds__(128) gather_kernel(
    const float* __restrict__ tpw, float* __restrict__ out, int N, float scale)
{
    __shared__ float sAcc[64][129];   // [row][node-in-block], pad 129 -> conflict-free
    __shared__ float sW[1024];        // tpw[4 paths][8][32]

    int tid = threadIdx.x;
    int node = blockIdx.x * 128 + tid;
    for (int i = tid; i < 1024; i += 128) sW[i] = __ldg(tpw + i);

    float acc[64];
#pragma unroll
    for (int k = 0; k < 64; k++) acc[k] = 0.0f;

    if (node < N) {
        int base = g_off[node];
        int end  = g_off[node + 1];
        int i = base;
        for (; i + 1 < end; i += 2) {
            const float4* P = g_pay + (size_t)i * 4;
            float4 a0 = P[0], a1 = P[1], a2 = P[2], a3 = P[3];
            float4 b0 = P[4], b1 = P[5], b2 = P[6], b3 = P[7];
            float sa[8] = { a0.x, a0.y, a0.z, a0.w, a1.x, a1.y, a1.z, a1.w };
            float aa[8] = { a2.x, a2.y, a2.z, a2.w, a3.x, a3.y, a3.z, a3.w };
            float sb[8] = { b0.x, b0.y, b0.z, b0.w, b1.x, b1.y, b1.z, b1.w };
            float ab[8] = { b2.x, b2.y, b2.z, b2.w, b3.x, b3.y, b3.z, b3.w };
#pragma unroll
            for (int j = 0; j < 8; j++)
#pragma unroll
                for (int u = 0; u < 8; u++)
                    acc[j * 8 + u] = fmaf(sa[j], aa[u], fmaf(sb[j], ab[u], acc[j * 8 + u]));
        }
        if (i < end) {
            const float4* P = g_pay + (size_t)i * 4;
            float4 a0 = P[0], a1 = P[1], a2 = P[2], a3 = P[3];
            float sa[8] = { a0.x, a0.y, a0.z, a0.w, a1.x, a1.y, a1.z, a1.w };
            float aa[8] = { a2.x, a2.y, a2.z, a2.w, a3.x, a3.y, a3.z, a3.w };
#pragma unroll
            for (int j = 0; j < 8; j++)
#pragma unroll
                for (int u = 0; u < 8; u++)
                    acc[j * 8 + u] = fmaf(sa[j], aa[u], acc[j * 8 + u]);
        }
    }

#pragma unroll
    for (int r = 0; r < 64; r++) sAcc[r][tid] = acc[r];
    __syncthreads();

    // finalize: thread = output column tid (0..127), loop nodes of this block
    float wa[8], wb[8];
    int ra, rb;
    if (tid < 32) {
        int v = tid;
#pragma unroll
        for (int u = 0; u < 8; u++) {
            wa[u] = sW[0 * 256 + u * 32 + v];   // W0 * alpha row
            wb[u] = sW[3 * 256 + u * 32 + v];   // W3 * beta row
        }
        ra = 0; rb = 8;
    } else {
        int q = tid - 32;
        int v = q / 3, o = q - 3 * v;
#pragma unroll
        for (int u = 0; u < 8; u++) {
            wa[u] = sW[1 * 256 + u * 32 + v];   // W1 * gamma*n_o rows
            wb[u] = sW[2 * 256 + u * 32 + v];   // W2 * delta*n_o rows
        }
        ra = (2 + o) * 8; rb = (5 + o) * 8;
    }

    int nmax = min(128, N - blockIdx.x * 128);
    for (int n = 0; n < nmax; n++) {
        float sum = 0.0f;
#pragma unroll
        for (int u = 0; u < 8; u++) {
            sum = fmaf(wa[u], sAcc[ra + u][n], sum);
            sum = fmaf(wb[u], sAcc[rb + u][n], sum);
        }
        out[(size_t)(blockIdx.x * 128 + n) * 128 + tid] = sum * scale;
    }
}

// ---------------- launch ----------------
extern "C" void kernel_launch(void* const* d_in, const int* in_sizes, int n_in,
                              void* d_out, int out_size)
{
    const float* pos       = (const float*)d_in[0];
    const int*   A         = (const int*)  d_in[1];
    const int*   esrc      = (const int*)  d_in[3];
    const int*   edst      = (const int*)  d_in[4];
    const float* shifts    = (const float*)d_in[5];
    const float* cell      = (const float*)d_in[6];
    const float* emb_table = (const float*)d_in[7];
    const float* w1  = (const float*)d_in[8];
    const float* b1  = (const float*)d_in[9];
    const float* w2  = (const float*)d_in[10];
    const float* b2  = (const float*)d_in[11];
    const float* f1  = (const float*)d_in[12];
    const float* fb1 = (const float*)d_in[13];
    const float* f2  = (const float*)d_in[14];
    const float* fb2 = (const float*)d_in[15];
    const float* f3  = (const float*)d_in[16];
    const float* fb3 = (const float*)d_in[17];
    const float* tpw = (const float*)d_in[18];

    int N = in_sizes[1];
    int E = in_sizes[3];

    int nbNode = (N + 255) / 256;
    int nbZero = (N + 2047) / 2048;
    prep_kernel<<<128 + nbNode + nbZero, 256>>>(f1, fb1, f2, fb2, f3, fb3,
                                                emb_table, A, w1, b1, w2, b2,
                                                pos, cell, N);
    count_kernel<<<(E / 4 + 255) / 256 + 1, 256>>>(edst, E);
    scan_kernel<<<1, 1024>>>(N);
    scatter_kernel<<<(E + 255) / 256, 256>>>(esrc, edst, shifts, cell, E);
    gather_kernel<<<(N + 127) / 128, 128>>>(tpw, (float*)d_out, N, (float)N / (float)E);
}